// round 2
// baseline (speedup 1.0000x reference)
#include <cuda_runtime.h>

#define T_LEN 512
#define BATCH 1024
#define INF   32
#define H     64
#define OUTF  32
#define BPB   8                  // batches per block
#define NBLK  (BATCH / BPB)      // 128 blocks
#define NTHR  128                // 4 warps; warp w owns j in [16w, 16w+16)
#define PAD_H 132                // 128 duplicated floats + 4 pad (bank spread)
#define PAD_X 68                 // 64 duplicated floats + 4 pad

typedef unsigned long long ull;

struct Smem {
    float W1T[INF][H];            // W1T[i][j]  = Wih1[j][i]
    float Wh1T[H][H];             // Wh1T[k][j] = Whh1[j][k]
    float W2T[H][H];
    float Wh2T[H][H];
    float hd1[2][BPB][PAD_H];     // h1 duplicated: hd1[..][b][2k]=hd1[..][b][2k+1]=h1[b][k]
    float hd2[2][BPB][PAD_H];
    float xsd[2][BPB][PAD_X];     // x duplicated
    float zfc[BPB][H];
};

__device__ __forceinline__ void fma2(ull& acc, ull a, ull b) {
    asm("fma.rn.f32x2 %0, %1, %2, %3;" : "=l"(acc) : "l"(a), "l"(b), "l"(acc));
}
__device__ __forceinline__ ull add2(ull a, ull b) {
    ull r; asm("add.rn.f32x2 %0, %1, %2;" : "=l"(r) : "l"(a), "l"(b)); return r;
}
__device__ __forceinline__ ull pack2(float x, float y) {
    ull r; asm("mov.b64 %0, {%1, %2};" : "=l"(r) : "f"(x), "f"(y)); return r;
}
__device__ __forceinline__ float2 unpack2(ull v) {
    float2 r; asm("mov.b64 {%0, %1}, %2;" : "=f"(r.x), "=f"(r.y) : "l"(v)); return r;
}

__device__ __forceinline__ float fast_tanh(float x) {
    float cx = fminf(fmaxf(x, -15.f), 15.f);
    float e;
    asm("ex2.approx.f32 %0, %1;" : "=f"(e) : "f"(cx * 2.8853900817779268f));
    float r;
    asm("rcp.approx.f32 %0, %1;" : "=f"(r) : "f"(e + 1.f));
    return (e - 1.f) * r;
}

// Accumulate a[j4..j4+3] += sum_k state[k] * W[k][j4..j4+3]
// state given duplicated: sd[2k] = sd[2k+1] = state[k]. Two acc banks (A even k, B odd k).
template<int KN>
__device__ __forceinline__ void gemm_pass(const float* __restrict__ sd,
                                          const float (*__restrict__ W)[H], int j4,
                                          ull& A01, ull& A23, ull& B01, ull& B23)
{
#pragma unroll
    for (int k = 0; k < KN; k += 2) {
        ulonglong2 hp = *(const ulonglong2*)(sd + 2 * k);     // (h_k,h_k),(h_k+1,h_k+1)
        ulonglong2 w0 = *(const ulonglong2*)&W[k][j4];        // (w0,w1),(w2,w3)
        ulonglong2 w1 = *(const ulonglong2*)&W[k + 1][j4];
        fma2(A01, hp.x, w0.x); fma2(A23, hp.x, w0.y);
        fma2(B01, hp.y, w1.x); fma2(B23, hp.y, w1.y);
    }
}

__global__ void __launch_bounds__(NTHR, 1)
rnn_fused_kernel(const float* __restrict__ x,
                 const float* __restrict__ Wih1, const float* __restrict__ Whh1,
                 const float* __restrict__ bih1, const float* __restrict__ bhh1,
                 const float* __restrict__ Wih2, const float* __restrict__ Whh2,
                 const float* __restrict__ bih2, const float* __restrict__ bhh2,
                 const float* __restrict__ Wfc1, const float* __restrict__ bfc1,
                 const float* __restrict__ Wfc2, const float* __restrict__ bfc2,
                 float* __restrict__ out)
{
    extern __shared__ float smem_raw[];
    Smem* s = reinterpret_cast<Smem*>(smem_raw);
    const int tid = threadIdx.x;

    // ---- weights to smem, transposed [k][j] ----
    for (int idx = tid; idx < H * INF; idx += NTHR) {
        int j = idx / INF, i = idx % INF;
        s->W1T[i][j] = Wih1[idx];
    }
    for (int idx = tid; idx < H * H; idx += NTHR) {
        int j = idx / H, k = idx % H;
        s->Wh1T[k][j] = Whh1[idx];
        s->W2T[k][j]  = Wih2[idx];
        s->Wh2T[k][j] = Whh2[idx];
    }

    // compute mapping: warp owns a j-quarter for all 8 batches
    const int lane = tid & 31, wrp = tid >> 5;
    const int b  = lane >> 2;            // 0..7
    const int jq = lane & 3;             // 0..3
    const int j4 = wrp * 16 + jq * 4;    // 4 outputs
    const int bg = blockIdx.x * BPB + b;

    // x loader mapping (coalesced)
    const int bx = tid >> 4, px = tid & 15;
    const float* xbL = x + (size_t)(blockIdx.x * BPB + bx) * T_LEN * INF;

    const ull pb1_01 = pack2(bih1[j4] + bhh1[j4],     bih1[j4 + 1] + bhh1[j4 + 1]);
    const ull pb1_23 = pack2(bih1[j4 + 2] + bhh1[j4 + 2], bih1[j4 + 3] + bhh1[j4 + 3]);
    const ull pb2_01 = pack2(bih2[j4] + bhh2[j4],     bih2[j4 + 1] + bhh2[j4 + 1]);
    const ull pb2_23 = pack2(bih2[j4 + 2] + bhh2[j4 + 2], bih2[j4 + 3] + bhh2[j4 + 3]);

    // init states (duplicated) and first x tile
    {
        float4 z4 = make_float4(0.f, 0.f, 0.f, 0.f);
        *(float4*)&s->hd1[0][b][2 * j4]     = z4;
        *(float4*)&s->hd1[0][b][2 * j4 + 4] = z4;
        *(float4*)&s->hd2[0][b][2 * j4]     = z4;
        *(float4*)&s->hd2[0][b][2 * j4 + 4] = z4;
        float2 x0 = *(const float2*)(xbL + px * 2);
        *(float4*)&s->xsd[0][bx][4 * px] = make_float4(x0.x, x0.x, x0.y, x0.y);
    }
    __syncthreads();

    int cur = 0;
    for (int t = 0; t < T_LEN; t++) {
        const int nb = cur ^ 1;
        float2 xn = make_float2(0.f, 0.f);
        if (t + 1 < T_LEN) xn = *(const float2*)(xbL + (t + 1) * INF + px * 2);

        // ---------- layer 1 ----------
        ull A01 = pb1_01, A23 = pb1_23, B01 = 0ull, B23 = 0ull;
        gemm_pass<INF>(&s->xsd[cur][b][0], s->W1T,  j4, A01, A23, B01, B23);
        gemm_pass<H>  (&s->hd1[cur][b][0], s->Wh1T, j4, A01, A23, B01, B23);
        {
            float2 v01 = unpack2(add2(A01, B01));
            float2 v23 = unpack2(add2(A23, B23));
            float n0 = fast_tanh(v01.x), n1 = fast_tanh(v01.y);
            float n2 = fast_tanh(v23.x), n3 = fast_tanh(v23.y);
            *(float4*)&s->hd1[nb][b][2 * j4]     = make_float4(n0, n0, n1, n1);
            *(float4*)&s->hd1[nb][b][2 * j4 + 4] = make_float4(n2, n2, n3, n3);
        }
        __syncthreads();   // new h1 visible to all warps

        // ---------- layer 2 ----------
        A01 = pb2_01; A23 = pb2_23; B01 = 0ull; B23 = 0ull;
        gemm_pass<H>(&s->hd1[nb][b][0],  s->W2T,  j4, A01, A23, B01, B23);
        gemm_pass<H>(&s->hd2[cur][b][0], s->Wh2T, j4, A01, A23, B01, B23);
        {
            float2 v01 = unpack2(add2(A01, B01));
            float2 v23 = unpack2(add2(A23, B23));
            float n0 = fast_tanh(v01.x), n1 = fast_tanh(v01.y);
            float n2 = fast_tanh(v23.x), n3 = fast_tanh(v23.y);
            *(float4*)&s->hd2[nb][b][2 * j4]     = make_float4(n0, n0, n1, n1);
            *(float4*)&s->hd2[nb][b][2 * j4 + 4] = make_float4(n2, n2, n3, n3);
        }
        // stage next x (duplicated)
        *(float4*)&s->xsd[nb][bx][4 * px] = make_float4(xn.x, xn.x, xn.y, xn.y);
        __syncthreads();   // h2 + x staged
        cur = nb;
    }

    // ---------- FC head ----------
    {
        float acc[4];
#pragma unroll
        for (int u = 0; u < 4; u++) acc[u] = bfc1[j4 + u];
#pragma unroll
        for (int k = 0; k < H; k += 2) {
            float4 hp = *(const float4*)&s->hd2[cur][b][2 * k];   // (hk,hk,hk+1,hk+1)
#pragma unroll
            for (int u = 0; u < 4; u++) {
                const float* wr = &Wfc1[(j4 + u) * H + k];
                acc[u] = fmaf(hp.x, wr[0], acc[u]);
                acc[u] = fmaf(hp.z, wr[1], acc[u]);
            }
        }
        s->zfc[b][j4 + 0] = fmaxf(acc[0], 0.f);
        s->zfc[b][j4 + 1] = fmaxf(acc[1], 0.f);
        s->zfc[b][j4 + 2] = fmaxf(acc[2], 0.f);
        s->zfc[b][j4 + 3] = fmaxf(acc[3], 0.f);
    }
    __syncthreads();
    {
        const int o0 = wrp * 8 + jq * 2, o1 = o0 + 1;
        float r0 = bfc2[o0], r1 = bfc2[o1];
#pragma unroll
        for (int k = 0; k < H; k += 4) {
            float4 zv = *(const float4*)&s->zfc[b][k];
            float4 w0 = *(const float4*)&Wfc2[o0 * H + k];
            float4 w1 = *(const float4*)&Wfc2[o1 * H + k];
            r0 += zv.x * w0.x + zv.y * w0.y + zv.z * w0.z + zv.w * w0.w;
            r1 += zv.x * w1.x + zv.y * w1.y + zv.z * w1.z + zv.w * w1.w;
        }
        out[bg * OUTF + o0] = r0;
        out[bg * OUTF + o1] = r1;
    }
}

extern "C" void kernel_launch(void* const* d_in, const int* in_sizes, int n_in,
                              void* d_out, int out_size)
{
    (void)in_sizes; (void)n_in; (void)out_size;
    const float* x    = (const float*)d_in[0];
    const float* Wih1 = (const float*)d_in[1];
    const float* Whh1 = (const float*)d_in[2];
    const float* bih1 = (const float*)d_in[3];
    const float* bhh1 = (const float*)d_in[4];
    const float* Wih2 = (const float*)d_in[5];
    const float* Whh2 = (const float*)d_in[6];
    const float* bih2 = (const float*)d_in[7];
    const float* bhh2 = (const float*)d_in[8];
    const float* Wfc1 = (const float*)d_in[9];
    const float* bfc1 = (const float*)d_in[10];
    const float* Wfc2 = (const float*)d_in[11];
    const float* bfc2 = (const float*)d_in[12];
    float* out = (float*)d_out;

    size_t smem = sizeof(Smem);
    cudaFuncSetAttribute(rnn_fused_kernel,
                         cudaFuncAttributeMaxDynamicSharedMemorySize, (int)smem);
    rnn_fused_kernel<<<NBLK, NTHR, smem>>>(x, Wih1, Whh1, bih1, bhh1,
                                           Wih2, Whh2, bih2, bhh2,
                                           Wfc1, bfc1, Wfc2, bfc2, out);
}

// round 3
// speedup vs baseline: 1.0029x; 1.0029x over previous
#include <cuda_runtime.h>

#define T_LEN 512
#define BATCH 1024
#define INF   32
#define H     64
#define OUTF  32
#define BPB   8
#define NBLK  (BATCH / BPB)   // 128 CTAs, 1 per SM
#define NTHR  256             // 8 warps

typedef unsigned long long ull;

// Weight layout per matrix: Wq[jp][2*kp + u] (ull), jp = j/2, kp = k/2,
//   Wq[jp][2*kp]   = pack(W[2jp  ][2kp], W[2jp  ][2kp+1])
//   Wq[jp][2*kp+1] = pack(W[2jp+1][2kp], W[2jp+1][2kp+1])
// Row stride K+2 ulls -> per-jp bank offset of 4 words (conflict-free).
struct Smem {
    ull   W1q[32][INF + 2];
    ull   Wh1q[32][H + 2];
    ull   W2q[32][H + 2];
    ull   Wh2q[32][H + 2];
    float h1[2][BPB][68];
    float h2[2][BPB][68];
    float xs[2][BPB][36];
    float zfc[BPB][68];
};

__device__ __forceinline__ void fma2(ull& acc, ull a, ull b) {
    asm("fma.rn.f32x2 %0, %1, %2, %3;" : "=l"(acc) : "l"(a), "l"(b), "l"(acc));
}
__device__ __forceinline__ ull add2(ull a, ull b) {
    ull r; asm("add.rn.f32x2 %0, %1, %2;" : "=l"(r) : "l"(a), "l"(b)); return r;
}
__device__ __forceinline__ ull pack2(float x, float y) {
    ull r; asm("mov.b64 %0, {%1, %2};" : "=l"(r) : "f"(x), "f"(y)); return r;
}
__device__ __forceinline__ float2 unpack2(ull v) {
    float2 r; asm("mov.b64 {%0, %1}, %2;" : "=f"(r.x), "=f"(r.y) : "l"(v)); return r;
}
__device__ __forceinline__ float fast_tanh(float x) {
    float cx = fminf(fmaxf(x, -15.f), 15.f);
    float e;
    asm("ex2.approx.f32 %0, %1;" : "=f"(e) : "f"(cx * 2.8853900817779268f));
    float r;
    asm("rcp.approx.f32 %0, %1;" : "=f"(r) : "f"(e + 1.f));
    return (e - 1.f) * r;
}

// acc[j0] split over f32x2 lanes as (even-k partial, odd-k partial).
template<int K>
__device__ __forceinline__ void gemm2(const float* __restrict__ st,
                                      const ull* __restrict__ wrow,
                                      ull& A0, ull& A1, ull& B0, ull& B1)
{
#pragma unroll
    for (int q = 0; q < K / 4; q++) {
        ulonglong2 hp = *(const ulonglong2*)(st + 4 * q);        // (h4q,h4q+1),(h4q+2,h4q+3)
        ulonglong2 w0 = *(const ulonglong2*)(wrow + 4 * q);      // kp=2q:  j0 pair, j1 pair
        ulonglong2 w1 = *(const ulonglong2*)(wrow + 4 * q + 2);  // kp=2q+1
        fma2(A0, hp.x, w0.x); fma2(A1, hp.x, w0.y);
        fma2(B0, hp.y, w1.x); fma2(B1, hp.y, w1.y);
    }
}

__global__ void __launch_bounds__(NTHR, 1)
rnn_fused_kernel(const float* __restrict__ x,
                 const float* __restrict__ Wih1, const float* __restrict__ Whh1,
                 const float* __restrict__ bih1, const float* __restrict__ bhh1,
                 const float* __restrict__ Wih2, const float* __restrict__ Whh2,
                 const float* __restrict__ bih2, const float* __restrict__ bhh2,
                 const float* __restrict__ Wfc1, const float* __restrict__ bfc1,
                 const float* __restrict__ Wfc2, const float* __restrict__ bfc2,
                 float* __restrict__ out)
{
    extern __shared__ float smem_raw[];
    Smem* s = reinterpret_cast<Smem*>(smem_raw);
    const int tid = threadIdx.x;

    // ---- fill weight smem in paired k-major layout ----
    {
        float* W1f  = (float*)s->W1q;
        float* Wh1f = (float*)s->Wh1q;
        float* W2f  = (float*)s->W2q;
        float* Wh2f = (float*)s->Wh2q;
        for (int idx = tid; idx < H * INF; idx += NTHR) {
            int j = idx / INF, k = idx % INF;
            int off = (j >> 1) * (INF + 2) * 2 + (k >> 1) * 4 + (j & 1) * 2 + (k & 1);
            W1f[off] = Wih1[idx];
        }
        for (int idx = tid; idx < H * H; idx += NTHR) {
            int j = idx / H, k = idx % H;
            int off = (j >> 1) * (H + 2) * 2 + (k >> 1) * 4 + (j & 1) * 2 + (k & 1);
            Wh1f[off] = Whh1[idx];
            W2f[off]  = Wih2[idx];
            Wh2f[off] = Whh2[idx];
        }
    }

    // compute mapping: warp w owns j in [8w, 8w+8); lane = (b, jpl)
    const int lane = tid & 31, wrp = tid >> 5;
    const int b   = lane >> 2;           // 0..7
    const int jpl = lane & 3;            // 0..3
    const int jp  = 4 * wrp + jpl;       // global j-pair 0..31
    const int j0  = 2 * jp;              // even j
    const int bg  = blockIdx.x * BPB + b;

    const ull* w1r  = &s->W1q[jp][0];
    const ull* wh1r = &s->Wh1q[jp][0];
    const ull* w2r  = &s->W2q[jp][0];
    const ull* wh2r = &s->Wh2q[jp][0];

    const ull pb1_0 = pack2(bih1[j0] + bhh1[j0], 0.f);
    const ull pb1_1 = pack2(bih1[j0 + 1] + bhh1[j0 + 1], 0.f);
    const ull pb2_0 = pack2(bih2[j0] + bhh2[j0], 0.f);
    const ull pb2_1 = pack2(bih2[j0 + 1] + bhh2[j0 + 1], 0.f);

    // x loader mapping: warp bL loads batch bL's 32 floats (coalesced 128B)
    const int bL = tid >> 5, iL = tid & 31;
    const float* xbL = x + (size_t)(blockIdx.x * BPB + bL) * T_LEN * INF;

    // init: zero h states (buffer 0), stage x[t=0]
    *(float2*)&s->h1[0][b][j0] = make_float2(0.f, 0.f);
    *(float2*)&s->h2[0][b][j0] = make_float2(0.f, 0.f);
    s->xs[0][bL][iL] = xbL[iL];
    __syncthreads();

    int cur = 0;
    for (int t = 0; t < T_LEN; t++) {
        const int nxt = cur ^ 1;
        float xn = 0.f;
        if (t + 1 < T_LEN) xn = xbL[(t + 1) * INF + iL];

        // ---------- layer 1: tanh(x@W1^T + h1@Wh1^T + b) ----------
        ull A0 = pb1_0, A1 = pb1_1, B0 = 0ull, B1 = 0ull;
        gemm2<INF>(&s->xs[cur][b][0], w1r,  A0, A1, B0, B1);
        gemm2<H>  (&s->h1[cur][b][0], wh1r, A0, A1, B0, B1);
        {
            float2 c0 = unpack2(add2(A0, B0));
            float2 c1 = unpack2(add2(A1, B1));
            float n0 = fast_tanh(c0.x + c0.y);
            float n1 = fast_tanh(c1.x + c1.y);
            *(float2*)&s->h1[nxt][b][j0] = make_float2(n0, n1);
        }
        __syncthreads();   // h1_t visible to all warps

        // ---------- layer 2: tanh(h1_t@W2^T + h2@Wh2^T + b) ----------
        A0 = pb2_0; A1 = pb2_1; B0 = 0ull; B1 = 0ull;
        gemm2<H>(&s->h1[nxt][b][0], w2r,  A0, A1, B0, B1);
        gemm2<H>(&s->h2[cur][b][0], wh2r, A0, A1, B0, B1);
        {
            float2 c0 = unpack2(add2(A0, B0));
            float2 c1 = unpack2(add2(A1, B1));
            float n0 = fast_tanh(c0.x + c0.y);
            float n1 = fast_tanh(c1.x + c1.y);
            *(float2*)&s->h2[nxt][b][j0] = make_float2(n0, n1);
        }
        s->xs[nxt][bL][iL] = xn;   // stage x_{t+1}
        __syncthreads();           // h2_t + x staged
        cur = nxt;
    }

    // ---------- FC head ----------
    {
        // z[j0], z[j0+1] for batch b
        float a0 = bfc1[j0], a1 = bfc1[j0 + 1];
        const float* hrow = &s->h2[cur][b][0];
#pragma unroll
        for (int k = 0; k < H; k += 4) {
            float4 hv = *(const float4*)(hrow + k);
            float4 wa = *(const float4*)&Wfc1[j0 * H + k];
            float4 wb = *(const float4*)&Wfc1[(j0 + 1) * H + k];
            a0 = fmaf(hv.x, wa.x, a0); a0 = fmaf(hv.y, wa.y, a0);
            a0 = fmaf(hv.z, wa.z, a0); a0 = fmaf(hv.w, wa.w, a0);
            a1 = fmaf(hv.x, wb.x, a1); a1 = fmaf(hv.y, wb.y, a1);
            a1 = fmaf(hv.z, wb.z, a1); a1 = fmaf(hv.w, wb.w, a1);
        }
        *(float2*)&s->zfc[b][j0] = make_float2(fmaxf(a0, 0.f), fmaxf(a1, 0.f));
    }
    __syncthreads();
    {
        const int b2 = tid >> 5, o = tid & 31;   // 8 batches x 32 outputs
        float r = bfc2[o];
        const float* zrow = &s->zfc[b2][0];
#pragma unroll
        for (int k = 0; k < H; k += 4) {
            float4 zv = *(const float4*)(zrow + k);
            float4 wv = *(const float4*)&Wfc2[o * H + k];
            r = fmaf(zv.x, wv.x, r); r = fmaf(zv.y, wv.y, r);
            r = fmaf(zv.z, wv.z, r); r = fmaf(zv.w, wv.w, r);
        }
        out[(blockIdx.x * BPB + b2) * OUTF + o] = r;
    }
}

extern "C" void kernel_launch(void* const* d_in, const int* in_sizes, int n_in,
                              void* d_out, int out_size)
{
    (void)in_sizes; (void)n_in; (void)out_size;
    const float* x    = (const float*)d_in[0];
    const float* Wih1 = (const float*)d_in[1];
    const float* Whh1 = (const float*)d_in[2];
    const float* bih1 = (const float*)d_in[3];
    const float* bhh1 = (const float*)d_in[4];
    const float* Wih2 = (const float*)d_in[5];
    const float* Whh2 = (const float*)d_in[6];
    const float* bih2 = (const float*)d_in[7];
    const float* bhh2 = (const float*)d_in[8];
    const float* Wfc1 = (const float*)d_in[9];
    const float* bfc1 = (const float*)d_in[10];
    const float* Wfc2 = (const float*)d_in[11];
    const float* bfc2 = (const float*)d_in[12];
    float* out = (float*)d_out;

    size_t smem = sizeof(Smem);
    cudaFuncSetAttribute(rnn_fused_kernel,
                         cudaFuncAttributeMaxDynamicSharedMemorySize, (int)smem);
    rnn_fused_kernel<<<NBLK, NTHR, smem>>>(x, Wih1, Whh1, bih1, bhh1,
                                           Wih2, Whh2, bih2, bhh2,
                                           Wfc1, bfc1, Wfc2, bfc2, out);
}

// round 4
// speedup vs baseline: 1.9783x; 1.9726x over previous
#include <cuda_runtime.h>

#define T_LEN 512
#define BATCH 1024
#define INF   32
#define H     64
#define OUTF  32
#define BPB   8
#define NBLK  (BATCH / BPB)   // 128 CTAs
#define NTHR  256             // 8 warps
#define SH    92              // h row stride (floats); chunk kg at offset kg*12
#define SPB   84              // partial-buffer b stride (s_j = 10)

typedef unsigned long long ull;

struct __align__(16) Smem {
    float h1[2][BPB][SH];
    float h2[2][BPB][SH];
    float part[8][8 * SPB];   // per-warp partial sums
    float zfc[BPB][H];
};

__device__ __forceinline__ void fma2(ull& acc, ull a, ull b) {
    asm("fma.rn.f32x2 %0, %1, %2, %3;" : "=l"(acc) : "l"(a), "l"(b), "l"(acc));
}
__device__ __forceinline__ ull add2(ull a, ull b) {
    ull r; asm("add.rn.f32x2 %0, %1, %2;" : "=l"(r) : "l"(a), "l"(b)); return r;
}
__device__ __forceinline__ float2 unpack2(ull v) {
    float2 r; asm("mov.b64 {%0, %1}, %2;" : "=f"(r.x), "=f"(r.y) : "l"(v)); return r;
}
__device__ __forceinline__ float fast_tanh(float x) {
    float cx = fminf(fmaxf(x, -15.f), 15.f);
    float e;
    asm("ex2.approx.f32 %0, %1;" : "=f"(e) : "f"(cx * 2.8853900817779268f));
    float r;
    asm("rcp.approx.f32 %0, %1;" : "=f"(r) : "f"(e + 1.f));
    return (e - 1.f) * r;
}

__global__ void __launch_bounds__(NTHR, 1)
rnn_fused_kernel(const float* __restrict__ x,
                 const float* __restrict__ Wih1, const float* __restrict__ Whh1,
                 const float* __restrict__ bih1, const float* __restrict__ bhh1,
                 const float* __restrict__ Wih2, const float* __restrict__ Whh2,
                 const float* __restrict__ bih2, const float* __restrict__ bhh2,
                 const float* __restrict__ Wfc1, const float* __restrict__ bfc1,
                 const float* __restrict__ Wfc2, const float* __restrict__ bfc2,
                 float* __restrict__ out)
{
    __shared__ Smem s;
    const int tid   = threadIdx.x;
    const int kg    = tid & 7;          // k-slice 0..7
    const int bg2   = (tid >> 3) & 1;   // batch half
    const int jg    = tid >> 4;         // j-group 0..15 (4 j's)
    const int wrp   = tid >> 5;
    const int jglow = jg & 1;
    const int lane  = tid & 31;
    const int j4  = jg * 4;
    const int bq  = bg2 * 4;
    const int kx0 = kg * 4;             // x k-slice (INF=32 over 8)
    const int kh0 = kg * 8;             // h k-slice (H=64 over 8)

    // ---- weights into registers (k-paired for f32x2) ----
    ull w1[4][2], wh1[4][4], w2r[4][4], wh2[4][4];
#pragma unroll
    for (int u = 0; u < 4; u++) {
        ulonglong2 a = *(const ulonglong2*)&Wih1[(j4 + u) * INF + kx0];
        w1[u][0] = a.x; w1[u][1] = a.y;
        ulonglong2 c0 = *(const ulonglong2*)&Whh1[(j4 + u) * H + kh0];
        ulonglong2 c1 = *(const ulonglong2*)&Whh1[(j4 + u) * H + kh0 + 4];
        wh1[u][0] = c0.x; wh1[u][1] = c0.y; wh1[u][2] = c1.x; wh1[u][3] = c1.y;
        ulonglong2 d0 = *(const ulonglong2*)&Wih2[(j4 + u) * H + kh0];
        ulonglong2 d1 = *(const ulonglong2*)&Wih2[(j4 + u) * H + kh0 + 4];
        w2r[u][0] = d0.x; w2r[u][1] = d0.y; w2r[u][2] = d1.x; w2r[u][3] = d1.y;
        ulonglong2 e0 = *(const ulonglong2*)&Whh2[(j4 + u) * H + kh0];
        ulonglong2 e1 = *(const ulonglong2*)&Whh2[(j4 + u) * H + kh0 + 4];
        wh2[u][0] = e0.x; wh2[u][1] = e0.y; wh2[u][2] = e1.x; wh2[u][3] = e1.y;
    }

    // finalize mapping: lane reduces outputs (b=lane>>3, j=wrp*8+(lane&7)) and (+4 batches)
    const int jf = wrp * 8 + (lane & 7);
    const float bA1 = bih1[jf] + bhh1[jf];
    const float bA2 = bih2[jf] + bhh2[jf];
    const int hw0 = (lane >> 3) * SH + wrp * 12 + (lane & 7);  // spread-chunk h index
    const int hw1 = hw0 + 4 * SH;

    float* pw = &s.part[wrp][bq * SPB + (jglow * 4) * 10 + kg];
    const float* prd = &s.part[wrp][(lane >> 3) * SPB + (lane & 7) * 10];

    const float* xp0 = x + (size_t)(blockIdx.x * BPB + bq) * T_LEN * INF + kx0;

    // zero h state
    for (int i = tid; i < 2 * BPB * SH; i += NTHR) {
        (&s.h1[0][0][0])[i] = 0.f;
        (&s.h2[0][0][0])[i] = 0.f;
    }
    ulonglong2 xc[4], xn[4];
#pragma unroll
    for (int ib = 0; ib < 4; ib++)
        xc[ib] = *(const ulonglong2*)(xp0 + (size_t)ib * T_LEN * INF);
    __syncthreads();

    int cur = 0;
    for (int t = 0; t < T_LEN; t++) {
        const int nxt = cur ^ 1;
        const int tn = (t + 1 < T_LEN) ? (t + 1) : (T_LEN - 1);
#pragma unroll
        for (int ib = 0; ib < 4; ib++)
            xn[ib] = *(const ulonglong2*)(xp0 + (size_t)ib * T_LEN * INF + (size_t)tn * INF);

        ull A[4][4];
        // ---------- layer 1 partials ----------
#pragma unroll
        for (int ib = 0; ib < 4; ib++) {
            const float* hb = &s.h1[cur][bq + ib][kg * 12];
            ulonglong2 h0 = *(const ulonglong2*)hb;
            ulonglong2 h1v = *(const ulonglong2*)(hb + 4);
            const ull xa = xc[ib].x, xb = xc[ib].y;
#pragma unroll
            for (int ij = 0; ij < 4; ij++) {
                ull acc = 0ull;
                fma2(acc, xa, w1[ij][0]);
                fma2(acc, xb, w1[ij][1]);
                fma2(acc, h0.x,  wh1[ij][0]);
                fma2(acc, h0.y,  wh1[ij][1]);
                fma2(acc, h1v.x, wh1[ij][2]);
                fma2(acc, h1v.y, wh1[ij][3]);
                A[ib][ij] = acc;
            }
        }
#pragma unroll
        for (int ib = 0; ib < 4; ib++)
#pragma unroll
            for (int ij = 0; ij < 4; ij++) {
                float2 f = unpack2(A[ib][ij]);
                pw[ib * SPB + ij * 10] = f.x + f.y;
            }
        __syncwarp();
        {   // reduce 8 k-slices (warp-local) -> tanh -> h1[nxt]
            ull p0 = *(const ull*)(prd);
            ull p1 = *(const ull*)(prd + 2);
            ull p2 = *(const ull*)(prd + 4);
            ull p3 = *(const ull*)(prd + 6);
            ull q0 = *(const ull*)(prd + 4 * SPB);
            ull q1 = *(const ull*)(prd + 4 * SPB + 2);
            ull q2 = *(const ull*)(prd + 4 * SPB + 4);
            ull q3 = *(const ull*)(prd + 4 * SPB + 6);
            float2 f0 = unpack2(add2(add2(p0, p1), add2(p2, p3)));
            float2 f1 = unpack2(add2(add2(q0, q1), add2(q2, q3)));
            (&s.h1[nxt][0][0])[hw0] = fast_tanh(f0.x + f0.y + bA1);
            (&s.h1[nxt][0][0])[hw1] = fast_tanh(f1.x + f1.y + bA1);
        }
        __syncthreads();

        // ---------- layer 2 partials ----------
#pragma unroll
        for (int ib = 0; ib < 4; ib++) {
            const float* hb1 = &s.h1[nxt][bq + ib][kg * 12];
            const float* hb2 = &s.h2[cur][bq + ib][kg * 12];
            ulonglong2 a0 = *(const ulonglong2*)hb1;
            ulonglong2 a1 = *(const ulonglong2*)(hb1 + 4);
            ulonglong2 b0 = *(const ulonglong2*)hb2;
            ulonglong2 b1 = *(const ulonglong2*)(hb2 + 4);
#pragma unroll
            for (int ij = 0; ij < 4; ij++) {
                ull acc = 0ull;
                fma2(acc, a0.x, w2r[ij][0]);
                fma2(acc, a0.y, w2r[ij][1]);
                fma2(acc, a1.x, w2r[ij][2]);
                fma2(acc, a1.y, w2r[ij][3]);
                fma2(acc, b0.x, wh2[ij][0]);
                fma2(acc, b0.y, wh2[ij][1]);
                fma2(acc, b1.x, wh2[ij][2]);
                fma2(acc, b1.y, wh2[ij][3]);
                A[ib][ij] = acc;
            }
        }
#pragma unroll
        for (int ib = 0; ib < 4; ib++)
#pragma unroll
            for (int ij = 0; ij < 4; ij++) {
                float2 f = unpack2(A[ib][ij]);
                pw[ib * SPB + ij * 10] = f.x + f.y;
            }
        __syncwarp();
        {
            ull p0 = *(const ull*)(prd);
            ull p1 = *(const ull*)(prd + 2);
            ull p2 = *(const ull*)(prd + 4);
            ull p3 = *(const ull*)(prd + 6);
            ull q0 = *(const ull*)(prd + 4 * SPB);
            ull q1 = *(const ull*)(prd + 4 * SPB + 2);
            ull q2 = *(const ull*)(prd + 4 * SPB + 4);
            ull q3 = *(const ull*)(prd + 4 * SPB + 6);
            float2 f0 = unpack2(add2(add2(p0, p1), add2(p2, p3)));
            float2 f1 = unpack2(add2(add2(q0, q1), add2(q2, q3)));
            (&s.h2[nxt][0][0])[hw0] = fast_tanh(f0.x + f0.y + bA2);
            (&s.h2[nxt][0][0])[hw1] = fast_tanh(f1.x + f1.y + bA2);
        }
#pragma unroll
        for (int ib = 0; ib < 4; ib++) xc[ib] = xn[ib];
        __syncthreads();
        cur = nxt;
    }

    // ---------- FC head (one-time) ----------
    {
        const int j = tid & 63;
        const int brow = tid >> 6;      // 0..3
#pragma unroll
        for (int rep = 0; rep < 2; rep++) {
            const int b = brow + rep * 4;
            float acc = bfc1[j];
#pragma unroll
            for (int c = 0; c < 8; c++) {
                const float* hb = &s.h2[cur][b][c * 12];
                const float* wr = &Wfc1[j * H + c * 8];
#pragma unroll
                for (int u = 0; u < 8; u++) acc = fmaf(hb[u], wr[u], acc);
            }
            s.zfc[b][j] = fmaxf(acc, 0.f);
        }
    }
    __syncthreads();
    {
        const int b = tid >> 5;
        const int o = tid & 31;
        float r = bfc2[o];
#pragma unroll
        for (int k = 0; k < H; k++) r = fmaf(s.zfc[b][k], Wfc2[o * H + k], r);
        out[(blockIdx.x * BPB + b) * OUTF + o] = r;
    }
}

extern "C" void kernel_launch(void* const* d_in, const int* in_sizes, int n_in,
                              void* d_out, int out_size)
{
    (void)in_sizes; (void)n_in; (void)out_size;
    const float* x    = (const float*)d_in[0];
    const float* Wih1 = (const float*)d_in[1];
    const float* Whh1 = (const float*)d_in[2];
    const float* bih1 = (const float*)d_in[3];
    const float* bhh1 = (const float*)d_in[4];
    const float* Wih2 = (const float*)d_in[5];
    const float* Whh2 = (const float*)d_in[6];
    const float* bih2 = (const float*)d_in[7];
    const float* bhh2 = (const float*)d_in[8];
    const float* Wfc1 = (const float*)d_in[9];
    const float* bfc1 = (const float*)d_in[10];
    const float* Wfc2 = (const float*)d_in[11];
    const float* bfc2 = (const float*)d_in[12];
    float* out = (float*)d_out;

    rnn_fused_kernel<<<NBLK, NTHR>>>(x, Wih1, Whh1, bih1, bhh1,
                                     Wih2, Whh2, bih2, bhh2,
                                     Wfc1, bfc1, Wfc2, bfc2, out);
}